// round 10
// baseline (speedup 1.0000x reference)
#include <cuda_runtime.h>

// Problem constants
#define Bsz   16
#define Lseq  4096
#define Dd    512
#define SPB   4          // d-lanes per tile (half tile -> 2 blocks/SM)
#define CH    32         // chunk length per thread
#define NCH   128        // chunks per sequence
#define NTH   512        // SPB * NCH
#define YSTR  33         // padded per-thread stride in Y
#define TILES (Bsz*(Dd/SPB))   // 2048

// smem floats: Y + RR(64) + PW(28) + PK(4) + VWT(128) + SWT(128) + XE + CV(8)
#define SMEM_FLOATS (NTH*YSTR + 64 + 28 + 4 + 128 + 128 + 2*NTH + 8)

__global__ void __launch_bounds__(NTH, 2)
iir_filtfilt_kernel(const float* __restrict__ x,
                    const float* __restrict__ bc,
                    const float* __restrict__ am,
                    float* __restrict__ out)
{
    extern __shared__ float sm[];
    float*  Y   = sm;                              // NTH*YSTR : x copy (for trend)
    float2* RR  = (float2*)(Y + NTH * YSTR);       // 32 : row0(A^(i+1))
    float*  PW  = (float*)(RR + CH);               // 28 : A^32..A^224 (7 mats)
    float*  PK  = PW + 28;                         // 4  : A^256
    float*  VWT = PK + 4;                          // 128 : warp aggregates [seq][w][2]
    float*  SWT = VWT + 128;                       // 128 : warp start states
    float*  XE  = SWT + 128;                       // 2*NTH : x-halos then y-edges
    float*  CV  = XE + 2 * NTH;                    // 8 : fwd(4)+bwd(4) boundary consts

    const int tid  = threadIdx.x;
    const int lane = tid & 31;
    const int wrp  = tid >> 5;                     // 0..15
    const int seq  = tid & 3;                      // 0..3
    const int ch   = tid >> 2;                     // 0..127
    const int g    = lane >> 2;                    // chunk-in-warp 0..7

    const float b0  = bc[0], b1 = bc[1], b2 = bc[2];
    const float na1 = am[0], na2 = am[1];          // A row0 = (-a1,-a2)
    const float bsum = b0 + b1 + b2;

    // Thread 0: RR[i]=row0(A^(i+1)); PW = A^32..A^224; PK = A^256.
    if (tid == 0) {
        float p00 = na1, p01 = na2, p10 = 1.f, p11 = 0.f;   // A^1
        RR[0] = make_float2(p00, p01);
        for (int i = 1; i < CH; ++i) {
            float q00 = fmaf(na1, p00, na2 * p10);
            float q01 = fmaf(na1, p01, na2 * p11);
            p10 = p00; p11 = p01; p00 = q00; p01 = q01;
            RR[i] = make_float2(p00, p01);
        }
        float a00 = p00, a01 = p01, a10 = p10, a11 = p11;   // A^32
        float c00 = a00, c01 = a01, c10 = a10, c11 = a11;
        PW[0] = c00; PW[1] = c01; PW[2] = c10; PW[3] = c11;
        for (int k = 1; k < 7; ++k) {
            float n00 = c00*a00 + c01*a10, n01 = c00*a01 + c01*a11;
            float n10 = c10*a00 + c11*a10, n11 = c10*a01 + c11*a11;
            c00 = n00; c01 = n01; c10 = n10; c11 = n11;
            PW[4*k] = c00; PW[4*k+1] = c01; PW[4*k+2] = c10; PW[4*k+3] = c11;
        }
        // A^256 = A^224 * A^32
        PK[0] = c00*a00 + c01*a10; PK[1] = c00*a01 + c01*a11;
        PK[2] = c10*a00 + c11*a10; PK[3] = c10*a01 + c11*a11;
    }

    const size_t OUTT = (size_t)Bsz * Lseq * Dd;

    for (int t = blockIdx.x; t < TILES; t += gridDim.x) {
        const int b  = t >> 7;                     // Dd/SPB = 128 tiles per batch
        const int d0 = (t & 127) * SPB;
        const float* xp = x + (size_t)b * Lseq * Dd + (size_t)ch * CH * Dd + d0 + seq;

        // Load own chunk to registers (front-batched; L2-hot after first tile).
        float xr[CH];
        #pragma unroll
        for (int i = 0; i < CH; ++i) xr[i] = xp[(size_t)i * Dd];

        __syncthreads();    // B1: previous tile finished reading Y/XE/CV/SWT

        #pragma unroll
        for (int i = 0; i < CH; ++i) Y[tid * YSTR + i] = xr[i];
        XE[2 * tid]     = xr[CH - 2];              // x halos for next chunk
        XE[2 * tid + 1] = xr[CH - 1];
        if (ch == 0) CV[seq] = bsum * xr[0];       // c_fwd
        __syncthreads();    // B2

        // Next-tile prefetch base (one prefetch per row; 128B line covers tile).
        int t2 = t + gridDim.x;  if (t2 >= TILES) t2 = t;
        const float* xpn = x + (size_t)(t2 >> 7) * Lseq * Dd
                             + (size_t)ch * CH * Dd + ((t2 & 127) * SPB);

        // ---------------- forward zero-init scan (p0 -> xr) ------------------
        float xm1, xm2;
        if (ch == 0) { xm1 = xr[0]; xm2 = xr[0]; }
        else { xm1 = XE[2*(tid-SPB)+1]; xm2 = XE[2*(tid-SPB)]; }
        float s0 = 0.f, s1 = 0.f;
        #pragma unroll
        for (int i = 0; i < CH; ++i) {
            if ((i & 3) == seq)
                asm volatile("prefetch.global.L2 [%0];" :: "l"(xpn + (size_t)i * Dd));
            float bx = fmaf(b2, xm2, fmaf(b1, xm1, b0 * xr[i]));
            xm2 = xm1; xm1 = xr[i];
            float ns = fmaf(na1, s0, fmaf(na2, s1, bx));
            s1 = s0; s0 = ns;
            xr[i] = ns;
        }

        // Intra-warp KS over the warp's 8 chunks/seq: hops 1,2,4 chunks.
        float v0 = s0, v1 = s1;
        #pragma unroll
        for (int st = 0; st < 3; ++st) {
            const int hc = 1 << st;                // hop in chunks
            const float* M = PW + 4 * (hc - 1);    // A^32, A^64, A^128
            float m00 = M[0], m01 = M[1], m10 = M[2], m11 = M[3];
            float u0 = __shfl_up_sync(0xffffffffu, v0, 4 * hc);
            float u1 = __shfl_up_sync(0xffffffffu, v1, 4 * hc);
            if (g < hc) { u0 = 0.f; u1 = 0.f; }
            v0 = fmaf(m00, u0, fmaf(m01, u1, v0));
            v1 = fmaf(m10, u0, fmaf(m11, u1, v1));
        }
        float E0 = __shfl_up_sync(0xffffffffu, v0, 4);
        float E1 = __shfl_up_sync(0xffffffffu, v1, 4);
        if (g == 0) { E0 = 0.f; E1 = 0.f; }
        if (g == 7) {
            VWT[(seq * 16 + wrp) * 2]     = v0;
            VWT[(seq * 16 + wrp) * 2 + 1] = v1;
        }
        __syncthreads();    // B3

        // Inter-warp combine: T_w = v_{w-1} + A^256·v_{w-2} (A^512 terms ~3e-21 dropped).
        if (wrp < 4) {
            int sx = wrp;
            float w0 = 0.f, w1 = 0.f;
            if (lane < 16) {
                w0 = VWT[(sx * 16 + lane) * 2];
                w1 = VWT[(sx * 16 + lane) * 2 + 1];
            }
            float c = CV[sx];
            float a0 = __shfl_up_sync(0xffffffffu, w0, 1);
            float a1 = __shfl_up_sync(0xffffffffu, w1, 1);
            float q0 = __shfl_up_sync(0xffffffffu, w0, 2);
            float q1 = __shfl_up_sync(0xffffffffu, w1, 2);
            if (lane == 1) { q0 = c; q1 = c; }
            float T0 = fmaf(PK[0], q0, fmaf(PK[1], q1, a0));
            float T1 = fmaf(PK[2], q0, fmaf(PK[3], q1, a1));
            if (lane == 0) { T0 = c; T1 = c; }
            if (lane < 16) {
                SWT[(sx * 16 + lane) * 2]     = T0;
                SWT[(sx * 16 + lane) * 2 + 1] = T1;
            }
        }
        __syncthreads();    // B4

        // Forward start state: ss = A^(32g)·T_w + E_g ; publish y-edges.
        float ss0, ss1;
        {
            float T0 = SWT[(seq * 16 + wrp) * 2], T1 = SWT[(seq * 16 + wrp) * 2 + 1];
            if (g == 0) { ss0 = T0; ss1 = T1; }
            else {
                const float* P = PW + 4 * (g - 1);
                ss0 = fmaf(P[0], T0, fmaf(P[1], T1, E0));
                ss1 = fmaf(P[2], T0, fmaf(P[3], T1, E1));
            }
        }
        float ylast = 0.f;
        {
            float2 r0 = RR[0], r1 = RR[1];
            XE[2 * tid]     = fmaf(r0.x, ss0, fmaf(r0.y, ss1, xr[0]));
            XE[2 * tid + 1] = fmaf(r1.x, ss0, fmaf(r1.y, ss1, xr[1]));
            if (ch == NCH - 1) {
                float2 rl = RR[CH - 1];
                ylast = fmaf(rl.x, ss0, fmaf(rl.y, ss1, xr[CH - 1]));
                CV[4 + seq] = bsum * ylast;
            }
        }
        __syncthreads();    // B5

        // ---------------- backward zero-init scan (p0_bwd -> xr) -------------
        float yp1, yp2;
        if (ch == NCH - 1) { yp1 = ylast; yp2 = ylast; }
        else { yp1 = XE[2*(tid+SPB)]; yp2 = XE[2*(tid+SPB)+1]; }
        s0 = 0.f; s1 = 0.f;
        #pragma unroll
        for (int i = CH - 1; i >= 0; --i) {
            float2 r = RR[i];
            float yv = fmaf(r.x, ss0, fmaf(r.y, ss1, xr[i]));
            float bx = fmaf(b2, yp2, fmaf(b1, yp1, b0 * yv));
            yp2 = yp1; yp1 = yv;
            float ns = fmaf(na1, s0, fmaf(na2, s1, bx));
            s1 = s0; s0 = ns;
            xr[i] = ns;
        }

        // Backward intra-warp KS (descending).
        v0 = s0; v1 = s1;
        #pragma unroll
        for (int st = 0; st < 3; ++st) {
            const int hc = 1 << st;
            const float* M = PW + 4 * (hc - 1);
            float m00 = M[0], m01 = M[1], m10 = M[2], m11 = M[3];
            float u0 = __shfl_down_sync(0xffffffffu, v0, 4 * hc);
            float u1 = __shfl_down_sync(0xffffffffu, v1, 4 * hc);
            if (g > 7 - hc) { u0 = 0.f; u1 = 0.f; }
            v0 = fmaf(m00, u0, fmaf(m01, u1, v0));
            v1 = fmaf(m10, u0, fmaf(m11, u1, v1));
        }
        E0 = __shfl_down_sync(0xffffffffu, v0, 4);
        E1 = __shfl_down_sync(0xffffffffu, v1, 4);
        if (g == 7) { E0 = 0.f; E1 = 0.f; }
        if (g == 0) {
            VWT[(seq * 16 + wrp) * 2]     = v0;
            VWT[(seq * 16 + wrp) * 2 + 1] = v1;
        }
        __syncthreads();    // B6

        // Backward inter-warp combine (mirror).
        if (wrp < 4) {
            int sx = wrp;
            float w0 = 0.f, w1 = 0.f;
            if (lane < 16) {
                w0 = VWT[(sx * 16 + lane) * 2];
                w1 = VWT[(sx * 16 + lane) * 2 + 1];
            }
            float c = CV[4 + sx];
            float a0 = __shfl_down_sync(0xffffffffu, w0, 1);
            float a1 = __shfl_down_sync(0xffffffffu, w1, 1);
            float q0 = __shfl_down_sync(0xffffffffu, w0, 2);
            float q1 = __shfl_down_sync(0xffffffffu, w1, 2);
            if (lane == 14) { q0 = c; q1 = c; }
            float T0 = fmaf(PK[0], q0, fmaf(PK[1], q1, a0));
            float T1 = fmaf(PK[2], q0, fmaf(PK[3], q1, a1));
            if (lane == 15) { T0 = c; T1 = c; }
            if (lane < 16) {
                SWT[(sx * 16 + lane) * 2]     = T0;
                SWT[(sx * 16 + lane) * 2 + 1] = T1;
            }
        }
        __syncthreads();    // B7

        // Backward start state: sb = A^(32(7-g))·T'_w + E'_g.
        float sb0, sb1;
        {
            float T0 = SWT[(seq * 16 + wrp) * 2], T1 = SWT[(seq * 16 + wrp) * 2 + 1];
            if (g == 7) { sb0 = T0; sb1 = T1; }
            else {
                const float* P = PW + 4 * (6 - g);
                sb0 = fmaf(P[0], T0, fmaf(P[1], T1, E0));
                sb1 = fmaf(P[2], T0, fmaf(P[3], T1, E1));
            }
        }

        // Final fix-up + streaming stores.
        float* os = out + (size_t)b * Lseq * Dd + (size_t)ch * CH * Dd + d0 + seq;
        float* ot = os + OUTT;
        #pragma unroll
        for (int i = 0; i < CH; ++i) {
            float2 r = RR[CH - 1 - i];
            float se = fmaf(r.x, sb0, fmaf(r.y, sb1, xr[i]));
            __stcs(os + (size_t)i * Dd, se);
            __stcs(ot + (size_t)i * Dd, Y[tid * YSTR + i] - se);
        }
    }
}

extern "C" void kernel_launch(void* const* d_in, const int* in_sizes, int n_in,
                              void* d_out, int out_size)
{
    const float* x  = (const float*)d_in[0];
    const float* bcp = (const float*)d_in[1];
    const float* amp = (const float*)d_in[2];
    float* out = (float*)d_out;

    int dev = 0;
    cudaGetDevice(&dev);
    int sms = 148;
    cudaDeviceGetAttribute(&sms, cudaDevAttrMultiProcessorCount, dev);

    int grid = 2 * sms;                    // 2 blocks per SM
    if (grid > TILES) grid = TILES;

    const size_t smem = (size_t)SMEM_FLOATS * sizeof(float);   // ~73 KB
    cudaFuncSetAttribute(iir_filtfilt_kernel,
                         cudaFuncAttributeMaxDynamicSharedMemorySize, (int)smem);

    iir_filtfilt_kernel<<<grid, NTH, smem>>>(x, bcp, amp, out);
}

// round 11
// speedup vs baseline: 1.7168x; 1.7168x over previous
#include <cuda_runtime.h>

// Problem constants
#define Bsz   16
#define Lseq  4096
#define Dd    512
#define SPB   8          // d-lanes per tile (full 32B sectors)
#define CH    20         // chunk length per thread
#define NCHB  64         // chunks per block per sequence
#define NTH   512        // SPB * NCHB
#define LE    1280       // extended L-span per tile (1024 core + halos)
#define LC    1024       // core L-span
#define YSTR  21         // padded per-thread stride in Y
#define TILES (Bsz*(Dd/SPB)*4)   // 16*64*4 = 4096

// smem floats: Y + RR(40) + PW(16) + PK(8) + VWT(264) + SWT(264) + XE(1024) + CV(16)
#define SMEM_FLOATS (NTH*YSTR + 40 + 16 + 8 + 264 + 264 + 2*NTH + 16)

__global__ void __launch_bounds__(NTH, 2)
iir_filtfilt_kernel(const float* __restrict__ x,
                    const float* __restrict__ bc,
                    const float* __restrict__ am,
                    float* __restrict__ out)
{
    extern __shared__ float sm[];
    float*  Y   = sm;                              // NTH*YSTR : x copy (for trend)
    float2* RR  = (float2*)(Y + NTH * YSTR);       // 20 : row0(A^(i+1))
    float*  PW  = (float*)(RR + CH);               // 16 : A^20,A^40,A^60,A^80
    float*  PK  = PW + 16;                         // 8  : A^160, A^320
    float*  VWT = PK + 8;                          // 264 : warp aggregates [seq][w][2], stride 33
    float*  SWT = VWT + 264;                       // 264 : warp start states
    float*  XE  = SWT + 264;                       // 2*NTH : x-halos then y-edges
    float*  CV  = XE + 2 * NTH;                    // 16 : fwd(8)+bwd(8) boundary consts

    const int tid  = threadIdx.x;
    const int lane = tid & 31;
    const int wrp  = tid >> 5;                     // 0..15
    const int seq  = tid & 7;                      // 0..7
    const int ch   = tid >> 3;                     // 0..63
    const int g    = lane >> 3;                    // chunk-in-warp 0..3

    const float b0  = bc[0], b1 = bc[1], b2 = bc[2];
    const float na1 = am[0], na2 = am[1];          // A row0 = (-a1,-a2)
    const float bsum = b0 + b1 + b2;               // == 0 exactly for this filter

    // Thread 0: RR[i]=row0(A^(i+1)) i<20; PW = A^20,A^40,A^60,A^80; PK = A^160,A^320.
    if (tid == 0) {
        float p00 = na1, p01 = na2, p10 = 1.f, p11 = 0.f;   // A^1
        RR[0] = make_float2(p00, p01);
        for (int i = 1; i < CH; ++i) {
            float q00 = fmaf(na1, p00, na2 * p10);
            float q01 = fmaf(na1, p01, na2 * p11);
            p10 = p00; p11 = p01; p00 = q00; p01 = q01;
            RR[i] = make_float2(p00, p01);
        }
        float a00 = p00, a01 = p01, a10 = p10, a11 = p11;   // A^20
        float c00 = a00, c01 = a01, c10 = a10, c11 = a11;
        PW[0] = c00; PW[1] = c01; PW[2] = c10; PW[3] = c11;
        for (int k = 1; k < 4; ++k) {                        // A^40, A^60, A^80
            float n00 = c00*a00 + c01*a10, n01 = c00*a01 + c01*a11;
            float n10 = c10*a00 + c11*a10, n11 = c10*a01 + c11*a11;
            c00 = n00; c01 = n01; c10 = n10; c11 = n11;
            PW[4*k] = c00; PW[4*k+1] = c01; PW[4*k+2] = c10; PW[4*k+3] = c11;
        }
        float d00 = c00*c00 + c01*c10, d01 = c00*c01 + c01*c11;   // A^160
        float d10 = c10*c00 + c11*c10, d11 = c10*c01 + c11*c11;
        PK[0] = d00; PK[1] = d01; PK[2] = d10; PK[3] = d11;
        float e00 = d00*d00 + d01*d10, e01 = d00*d01 + d01*d11;   // A^320
        float e10 = d10*d00 + d11*d10, e11 = d10*d01 + d11*d11;
        PK[4] = e00; PK[5] = e01; PK[6] = e10; PK[7] = e11;
    }

    const size_t OUTT = (size_t)Bsz * Lseq * Dd;

    for (int t = blockIdx.x; t < TILES; t += gridDim.x) {
        const int b    = t >> 8;                   // 256 tiles per batch
        const int dgrp = (t >> 2) & 63;
        const int q    = t & 3;
        const int d0   = dgrp * SPB;
        const int l0   = q << 10;                  // core start
        int elo = l0 - 128;                        // window start (halo)
        if (elo < 0) elo = 0;
        if (elo > Lseq - LE) elo = Lseq - LE;

        const int lbase = elo + ch * CH;           // this thread's first l
        const float* xp = x + (size_t)b * Lseq * Dd + (size_t)lbase * Dd + d0 + seq;

        // Load own chunk to registers (front-batched; all l in range by construction).
        float xr[CH];
        #pragma unroll
        for (int i = 0; i < CH; ++i) xr[i] = xp[(size_t)i * Dd];

        __syncthreads();    // B1: previous tile finished reading Y/XE/CV/SWT

        #pragma unroll
        for (int i = 0; i < CH; ++i) Y[tid * YSTR + i] = xr[i];
        XE[2 * tid]     = xr[CH - 2];              // x halos for next chunk
        XE[2 * tid + 1] = xr[CH - 1];
        if (ch == 0) CV[seq] = bsum * xr[0];       // c_fwd (exact 0; exact ref init at q0)
        __syncthreads();    // B2

        // Next-tile prefetch (one prefetch per 32B row-sector, deduped by seq).
        int t2 = t + gridDim.x;  if (t2 >= TILES) t2 = t;
        int elo2 = ((t2 & 3) << 10) - 128;
        if (elo2 < 0) elo2 = 0;
        if (elo2 > Lseq - LE) elo2 = Lseq - LE;
        const float* xpn = x + (size_t)(t2 >> 8) * Lseq * Dd
                             + (size_t)(elo2 + ch * CH) * Dd + (((t2 >> 2) & 63) * SPB);

        // ---------------- forward zero-init scan (p0 -> xr) ------------------
        float xm1, xm2;
        if (ch == 0) { xm1 = xr[0]; xm2 = xr[0]; }          // edge/warm-up replicate
        else { xm1 = XE[2*(tid-SPB)+1]; xm2 = XE[2*(tid-SPB)]; }
        float s0 = 0.f, s1 = 0.f;
        #pragma unroll
        for (int i = 0; i < CH; ++i) {
            if ((i & 7) == seq)
                asm volatile("prefetch.global.L2 [%0];" :: "l"(xpn + (size_t)i * Dd));
            float bx = fmaf(b2, xm2, fmaf(b1, xm1, b0 * xr[i]));
            xm2 = xm1; xm1 = xr[i];
            float ns = fmaf(na1, s0, fmaf(na2, s1, bx));
            s1 = s0; s0 = ns;
            xr[i] = ns;
        }

        // Intra-warp KS over the warp's 4 chunks: hops 1 (A^20), 2 (A^40).
        float v0 = s0, v1 = s1;
        #pragma unroll
        for (int st = 0; st < 2; ++st) {
            const int hc = 1 << st;
            const float* M = PW + 4 * (hc - 1);    // A^20, A^40
            float m00 = M[0], m01 = M[1], m10 = M[2], m11 = M[3];
            float u0 = __shfl_up_sync(0xffffffffu, v0, 8 * hc);
            float u1 = __shfl_up_sync(0xffffffffu, v1, 8 * hc);
            if (g < hc) { u0 = 0.f; u1 = 0.f; }
            v0 = fmaf(m00, u0, fmaf(m01, u1, v0));
            v1 = fmaf(m10, u0, fmaf(m11, u1, v1));
        }
        float E0 = __shfl_up_sync(0xffffffffu, v0, 8);
        float E1 = __shfl_up_sync(0xffffffffu, v1, 8);
        if (g == 0) { E0 = 0.f; E1 = 0.f; }
        if (g == 3) {
            VWT[seq * 33 + 2 * wrp]     = v0;
            VWT[seq * 33 + 2 * wrp + 1] = v1;
        }
        __syncthreads();    // B3

        // Inter-warp KS over 16 warp aggregates (warp s = seq s, lanes 0..15).
        // Hops 1,2,4 with A^80, A^160, A^320 (hop-8 terms ~e-59: dropped).
        if (wrp < 8) {
            int s = wrp;
            float w0 = 0.f, w1 = 0.f;
            if (lane < 16) {
                w0 = VWT[s * 33 + 2 * lane];
                w1 = VWT[s * 33 + 2 * lane + 1];
            }
            float c = CV[s];
            if (lane == 0) {                       // inject A^80 * [c,c]
                w0 = fmaf(PW[12] + PW[13], c, w0);
                w1 = fmaf(PW[14] + PW[15], c, w1);
            }
            #pragma unroll
            for (int st = 0; st < 3; ++st) {
                const int hc = 1 << st;
                const float* M = (st == 0) ? (PW + 12) : (PK + 4 * (st - 1));
                float m00 = M[0], m01 = M[1], m10 = M[2], m11 = M[3];
                float u0 = __shfl_up_sync(0xffffffffu, w0, hc);
                float u1 = __shfl_up_sync(0xffffffffu, w1, hc);
                if (lane < hc) { u0 = 0.f; u1 = 0.f; }
                w0 = fmaf(m00, u0, fmaf(m01, u1, w0));
                w1 = fmaf(m10, u0, fmaf(m11, u1, w1));
            }
            float T0 = __shfl_up_sync(0xffffffffu, w0, 1);
            float T1 = __shfl_up_sync(0xffffffffu, w1, 1);
            if (lane == 0) { T0 = c; T1 = c; }
            if (lane < 16) {
                SWT[s * 33 + 2 * lane]     = T0;
                SWT[s * 33 + 2 * lane + 1] = T1;
            }
        }
        __syncthreads();    // B4

        // Forward start state: ss = A^(20g)·T_w + E_g ; publish y-edges.
        float ss0, ss1;
        {
            float T0 = SWT[seq * 33 + 2 * wrp], T1 = SWT[seq * 33 + 2 * wrp + 1];
            if (g == 0) { ss0 = T0; ss1 = T1; }
            else {
                const float* P = PW + 4 * (g - 1);
                ss0 = fmaf(P[0], T0, fmaf(P[1], T1, E0));
                ss1 = fmaf(P[2], T0, fmaf(P[3], T1, E1));
            }
        }
        float ylast = 0.f;
        {
            float2 r0 = RR[0], r1 = RR[1];
            XE[2 * tid]     = fmaf(r0.x, ss0, fmaf(r0.y, ss1, xr[0]));
            XE[2 * tid + 1] = fmaf(r1.x, ss0, fmaf(r1.y, ss1, xr[1]));
            if (ch == NCHB - 1) {
                float2 rl = RR[CH - 1];
                ylast = fmaf(rl.x, ss0, fmaf(rl.y, ss1, xr[CH - 1]));
                CV[8 + seq] = bsum * ylast;        // c_bwd (exact 0)
            }
        }
        __syncthreads();    // B5

        // ---------------- backward zero-init scan (p0_bwd -> xr) -------------
        float yp1, yp2;
        if (ch == NCHB - 1) { yp1 = ylast; yp2 = ylast; }   // edge/warm-up replicate
        else { yp1 = XE[2*(tid+SPB)]; yp2 = XE[2*(tid+SPB)+1]; }
        s0 = 0.f; s1 = 0.f;
        #pragma unroll
        for (int i = CH - 1; i >= 0; --i) {
            float2 r = RR[i];
            float yv = fmaf(r.x, ss0, fmaf(r.y, ss1, xr[i]));
            float bx = fmaf(b2, yp2, fmaf(b1, yp1, b0 * yv));
            yp2 = yp1; yp1 = yv;
            float ns = fmaf(na1, s0, fmaf(na2, s1, bx));
            s1 = s0; s0 = ns;
            xr[i] = ns;
        }

        // Backward intra-warp KS (descending).
        v0 = s0; v1 = s1;
        #pragma unroll
        for (int st = 0; st < 2; ++st) {
            const int hc = 1 << st;
            const float* M = PW + 4 * (hc - 1);
            float m00 = M[0], m01 = M[1], m10 = M[2], m11 = M[3];
            float u0 = __shfl_down_sync(0xffffffffu, v0, 8 * hc);
            float u1 = __shfl_down_sync(0xffffffffu, v1, 8 * hc);
            if (g > 3 - hc) { u0 = 0.f; u1 = 0.f; }
            v0 = fmaf(m00, u0, fmaf(m01, u1, v0));
            v1 = fmaf(m10, u0, fmaf(m11, u1, v1));
        }
        E0 = __shfl_down_sync(0xffffffffu, v0, 8);
        E1 = __shfl_down_sync(0xffffffffu, v1, 8);
        if (g == 3) { E0 = 0.f; E1 = 0.f; }
        if (g == 0) {
            VWT[seq * 33 + 2 * wrp]     = v0;
            VWT[seq * 33 + 2 * wrp + 1] = v1;
        }
        __syncthreads();    // B6

        // Backward inter-warp KS (mirror).
        if (wrp < 8) {
            int s = wrp;
            float w0 = 0.f, w1 = 0.f;
            if (lane < 16) {
                w0 = VWT[s * 33 + 2 * lane];
                w1 = VWT[s * 33 + 2 * lane + 1];
            }
            float c = CV[8 + s];
            if (lane == 15) {
                w0 = fmaf(PW[12] + PW[13], c, w0);
                w1 = fmaf(PW[14] + PW[15], c, w1);
            }
            #pragma unroll
            for (int st = 0; st < 3; ++st) {
                const int hc = 1 << st;
                const float* M = (st == 0) ? (PW + 12) : (PK + 4 * (st - 1));
                float m00 = M[0], m01 = M[1], m10 = M[2], m11 = M[3];
                float u0 = __shfl_down_sync(0xffffffffu, w0, hc);
                float u1 = __shfl_down_sync(0xffffffffu, w1, hc);
                if (lane > 15 - hc) { u0 = 0.f; u1 = 0.f; }
                w0 = fmaf(m00, u0, fmaf(m01, u1, w0));
                w1 = fmaf(m10, u0, fmaf(m11, u1, w1));
            }
            float T0 = __shfl_down_sync(0xffffffffu, w0, 1);
            float T1 = __shfl_down_sync(0xffffffffu, w1, 1);
            if (lane == 15) { T0 = c; T1 = c; }
            if (lane < 16) {
                SWT[s * 33 + 2 * lane]     = T0;
                SWT[s * 33 + 2 * lane + 1] = T1;
            }
        }
        __syncthreads();    // B7

        // Backward start state: sb = A^(20(3-g))·T'_w + E'_g.
        float sb0, sb1;
        {
            float T0 = SWT[seq * 33 + 2 * wrp], T1 = SWT[seq * 33 + 2 * wrp + 1];
            if (g == 3) { sb0 = T0; sb1 = T1; }
            else {
                const float* P = PW + 4 * (2 - g);
                sb0 = fmaf(P[0], T0, fmaf(P[1], T1, E0));
                sb1 = fmaf(P[2], T0, fmaf(P[3], T1, E1));
            }
        }

        // Final fix-up + predicated streaming stores (core region only).
        float* os = out + (size_t)b * Lseq * Dd + (size_t)lbase * Dd + d0 + seq;
        float* ot = os + OUTT;
        const int coff = lbase - l0;               // position of i=0 relative to core
        #pragma unroll
        for (int i = 0; i < CH; ++i) {
            float2 r = RR[CH - 1 - i];
            float se = fmaf(r.x, sb0, fmaf(r.y, sb1, xr[i]));
            if ((unsigned)(coff + i) < (unsigned)LC) {
                __stcs(os + (size_t)i * Dd, se);
                __stcs(ot + (size_t)i * Dd, Y[tid * YSTR + i] - se);
            }
        }
    }
}

extern "C" void kernel_launch(void* const* d_in, const int* in_sizes, int n_in,
                              void* d_out, int out_size)
{
    const float* x  = (const float*)d_in[0];
    const float* bcp = (const float*)d_in[1];
    const float* amp = (const float*)d_in[2];
    float* out = (float*)d_out;

    int dev = 0;
    cudaGetDevice(&dev);
    int sms = 148;
    cudaDeviceGetAttribute(&sms, cudaDevAttrMultiProcessorCount, dev);

    int grid = 2 * sms;                    // 2 blocks per SM (independent phase domains)
    if (grid > TILES) grid = TILES;

    const size_t smem = (size_t)SMEM_FLOATS * sizeof(float);   // ~50 KB
    cudaFuncSetAttribute(iir_filtfilt_kernel,
                         cudaFuncAttributeMaxDynamicSharedMemorySize, (int)smem);

    iir_filtfilt_kernel<<<grid, NTH, smem>>>(x, bcp, amp, out);
}

// round 12
// speedup vs baseline: 2.0134x; 1.1727x over previous
#include <cuda_runtime.h>

// Problem constants
#define Bsz   16
#define Lseq  4096
#define Dd    512
#define SPB   8          // d-lanes per tile (full 32B sectors)
#define CH    34         // chunk length per thread
#define NCHB  64         // chunks per block per sequence
#define NTH   512        // SPB * NCHB
#define LE    2176       // extended L-span per tile (2048 core + 128 halo)
#define LC    2048       // core L-span
#define YSTR  35         // padded per-thread stride in Y
#define TILES (Bsz*(Dd/SPB)*2)   // 16*64*2 = 2048

// smem floats: Y + RR(68) + PW(16) + PK(8) + VWT(264) + SWT(264) + XE(1024) + CV(16)
#define SMEM_FLOATS (NTH*YSTR + 68 + 16 + 8 + 264 + 264 + 2*NTH + 16)

__global__ void __launch_bounds__(NTH, 2)
iir_filtfilt_kernel(const float* __restrict__ x,
                    const float* __restrict__ bc,
                    const float* __restrict__ am,
                    float* __restrict__ out)
{
    extern __shared__ float sm[];
    float*  Y   = sm;                              // NTH*YSTR : x copy (for trend)
    float2* RR  = (float2*)(Y + NTH * YSTR);       // 34 : row0(A^(i+1))
    float*  PW  = (float*)(RR + CH);               // 16 : A^34,A^68,A^102,A^136
    float*  PK  = PW + 16;                         // 8  : A^272, A^544
    float*  VWT = PK + 8;                          // 264 : warp aggregates [seq][w][2], stride 33
    float*  SWT = VWT + 264;                       // 264 : warp start states
    float*  XE  = SWT + 264;                       // 2*NTH : x-halos then y-edges
    float*  CV  = XE + 2 * NTH;                    // 16 : fwd(8)+bwd(8) boundary consts

    const int tid  = threadIdx.x;
    const int lane = tid & 31;
    const int wrp  = tid >> 5;                     // 0..15
    const int seq  = tid & 7;                      // 0..7
    const int ch   = tid >> 3;                     // 0..63
    const int g    = lane >> 3;                    // chunk-in-warp 0..3

    const float b0  = bc[0], b1 = bc[1], b2 = bc[2];
    const float na1 = am[0], na2 = am[1];          // A row0 = (-a1,-a2)
    const float bsum = b0 + b1 + b2;               // == 0 exactly for this filter

    // Thread 0: RR[i]=row0(A^(i+1)) i<34; PW = A^34..A^136; PK = A^272, A^544.
    if (tid == 0) {
        float p00 = na1, p01 = na2, p10 = 1.f, p11 = 0.f;   // A^1
        RR[0] = make_float2(p00, p01);
        for (int i = 1; i < CH; ++i) {
            float q00 = fmaf(na1, p00, na2 * p10);
            float q01 = fmaf(na1, p01, na2 * p11);
            p10 = p00; p11 = p01; p00 = q00; p01 = q01;
            RR[i] = make_float2(p00, p01);
        }
        float a00 = p00, a01 = p01, a10 = p10, a11 = p11;   // A^34
        float c00 = a00, c01 = a01, c10 = a10, c11 = a11;
        PW[0] = c00; PW[1] = c01; PW[2] = c10; PW[3] = c11;
        for (int k = 1; k < 4; ++k) {                        // A^68, A^102, A^136
            float n00 = c00*a00 + c01*a10, n01 = c00*a01 + c01*a11;
            float n10 = c10*a00 + c11*a10, n11 = c10*a01 + c11*a11;
            c00 = n00; c01 = n01; c10 = n10; c11 = n11;
            PW[4*k] = c00; PW[4*k+1] = c01; PW[4*k+2] = c10; PW[4*k+3] = c11;
        }
        float d00 = c00*c00 + c01*c10, d01 = c00*c01 + c01*c11;   // A^272
        float d10 = c10*c00 + c11*c10, d11 = c10*c01 + c11*c11;
        PK[0] = d00; PK[1] = d01; PK[2] = d10; PK[3] = d11;
        float e00 = d00*d00 + d01*d10, e01 = d00*d01 + d01*d11;   // A^544
        float e10 = d10*d00 + d11*d10, e11 = d10*d01 + d11*d11;
        PK[4] = e00; PK[5] = e01; PK[6] = e10; PK[7] = e11;
    }

    const size_t OUTT = (size_t)Bsz * Lseq * Dd;

    for (int t = blockIdx.x; t < TILES; t += gridDim.x) {
        const int b    = t >> 7;                   // 128 tiles per batch
        const int dgrp = (t >> 1) & 63;
        const int h    = t & 1;                    // L-half 0/1
        const int d0   = dgrp * SPB;
        const int elo  = h ? (Lseq - LE) : 0;      // window start (1920 or 0)

        const int lbase = elo + ch * CH;           // this thread's first l
        const float* xp = x + (size_t)b * Lseq * Dd + (size_t)lbase * Dd + d0 + seq;

        // Load own chunk to registers (front-batched).
        float xr[CH];
        #pragma unroll
        for (int i = 0; i < CH; ++i) xr[i] = xp[(size_t)i * Dd];

        __syncthreads();    // B1: previous tile finished reading Y/XE/CV/SWT

        #pragma unroll
        for (int i = 0; i < CH; ++i) Y[tid * YSTR + i] = xr[i];
        XE[2 * tid]     = xr[CH - 2];              // x halos for next chunk
        XE[2 * tid + 1] = xr[CH - 1];
        if (ch == 0) CV[seq] = bsum * xr[0];       // c_fwd (==0 exactly; exact ref init at h=0)
        __syncthreads();    // B2

        // Next-tile prefetch (deduped: one per 32B row-sector by seq).
        int t2 = t + gridDim.x;  if (t2 >= TILES) t2 = t;
        const int elo2 = (t2 & 1) ? (Lseq - LE) : 0;
        const float* xpn = x + (size_t)(t2 >> 7) * Lseq * Dd
                             + (size_t)(elo2 + ch * CH) * Dd + (((t2 >> 1) & 63) * SPB);

        // ---------------- forward zero-init scan (p0 -> xr) ------------------
        float xm1, xm2;
        if (ch == 0) { xm1 = xr[0]; xm2 = xr[0]; }          // edge/warm-up replicate
        else { xm1 = XE[2*(tid-SPB)+1]; xm2 = XE[2*(tid-SPB)]; }
        float s0 = 0.f, s1 = 0.f;
        #pragma unroll
        for (int i = 0; i < CH; ++i) {
            if ((i & 7) == seq)
                asm volatile("prefetch.global.L2 [%0];" :: "l"(xpn + (size_t)i * Dd));
            float bx = fmaf(b2, xm2, fmaf(b1, xm1, b0 * xr[i]));
            xm2 = xm1; xm1 = xr[i];
            float ns = fmaf(na1, s0, fmaf(na2, s1, bx));
            s1 = s0; s0 = ns;
            xr[i] = ns;
        }

        // Intra-warp KS over the warp's 4 chunks: hops 1 (A^34), 2 (A^68).
        float v0 = s0, v1 = s1;
        #pragma unroll
        for (int st = 0; st < 2; ++st) {
            const int hc = 1 << st;
            const float* M = PW + 4 * (hc - 1);
            float m00 = M[0], m01 = M[1], m10 = M[2], m11 = M[3];
            float u0 = __shfl_up_sync(0xffffffffu, v0, 8 * hc);
            float u1 = __shfl_up_sync(0xffffffffu, v1, 8 * hc);
            if (g < hc) { u0 = 0.f; u1 = 0.f; }
            v0 = fmaf(m00, u0, fmaf(m01, u1, v0));
            v1 = fmaf(m10, u0, fmaf(m11, u1, v1));
        }
        float E0 = __shfl_up_sync(0xffffffffu, v0, 8);
        float E1 = __shfl_up_sync(0xffffffffu, v1, 8);
        if (g == 0) { E0 = 0.f; E1 = 0.f; }
        if (g == 3) {
            VWT[seq * 33 + 2 * wrp]     = v0;
            VWT[seq * 33 + 2 * wrp + 1] = v1;
        }
        __syncthreads();    // B3

        // Inter-warp KS over 16 warp aggregates (warp s = seq s, lanes 0..15).
        // Hops 1,2,4 with A^136, A^272, A^544 (hop-8 terms ~1e-44: dropped).
        if (wrp < 8) {
            int s = wrp;
            float w0 = 0.f, w1 = 0.f;
            if (lane < 16) {
                w0 = VWT[s * 33 + 2 * lane];
                w1 = VWT[s * 33 + 2 * lane + 1];
            }
            float c = CV[s];
            if (lane == 0) {                       // inject A^136 * [c,c]
                w0 = fmaf(PW[12] + PW[13], c, w0);
                w1 = fmaf(PW[14] + PW[15], c, w1);
            }
            #pragma unroll
            for (int st = 0; st < 3; ++st) {
                const int hc = 1 << st;
                const float* M = (st == 0) ? (PW + 12) : (PK + 4 * (st - 1));
                float m00 = M[0], m01 = M[1], m10 = M[2], m11 = M[3];
                float u0 = __shfl_up_sync(0xffffffffu, w0, hc);
                float u1 = __shfl_up_sync(0xffffffffu, w1, hc);
                if (lane < hc) { u0 = 0.f; u1 = 0.f; }
                w0 = fmaf(m00, u0, fmaf(m01, u1, w0));
                w1 = fmaf(m10, u0, fmaf(m11, u1, w1));
            }
            float T0 = __shfl_up_sync(0xffffffffu, w0, 1);
            float T1 = __shfl_up_sync(0xffffffffu, w1, 1);
            if (lane == 0) { T0 = c; T1 = c; }
            if (lane < 16) {
                SWT[s * 33 + 2 * lane]     = T0;
                SWT[s * 33 + 2 * lane + 1] = T1;
            }
        }
        __syncthreads();    // B4

        // Forward start state: ss = A^(34g)·T_w + E_g ; publish y-edges.
        float ss0, ss1;
        {
            float T0 = SWT[seq * 33 + 2 * wrp], T1 = SWT[seq * 33 + 2 * wrp + 1];
            if (g == 0) { ss0 = T0; ss1 = T1; }
            else {
                const float* P = PW + 4 * (g - 1);
                ss0 = fmaf(P[0], T0, fmaf(P[1], T1, E0));
                ss1 = fmaf(P[2], T0, fmaf(P[3], T1, E1));
            }
        }
        float ylast = 0.f;
        {
            float2 r0 = RR[0], r1 = RR[1];
            XE[2 * tid]     = fmaf(r0.x, ss0, fmaf(r0.y, ss1, xr[0]));
            XE[2 * tid + 1] = fmaf(r1.x, ss0, fmaf(r1.y, ss1, xr[1]));
            if (ch == NCHB - 1) {
                float2 rl = RR[CH - 1];
                ylast = fmaf(rl.x, ss0, fmaf(rl.y, ss1, xr[CH - 1]));
                CV[8 + seq] = bsum * ylast;        // c_bwd (==0 exactly; exact at h=1)
            }
        }
        __syncthreads();    // B5

        // ---------------- backward zero-init scan (p0_bwd -> xr) -------------
        float yp1, yp2;
        if (ch == NCHB - 1) { yp1 = ylast; yp2 = ylast; }   // edge/warm-up replicate
        else { yp1 = XE[2*(tid+SPB)]; yp2 = XE[2*(tid+SPB)+1]; }
        s0 = 0.f; s1 = 0.f;
        #pragma unroll
        for (int i = CH - 1; i >= 0; --i) {
            float2 r = RR[i];
            float yv = fmaf(r.x, ss0, fmaf(r.y, ss1, xr[i]));
            float bx = fmaf(b2, yp2, fmaf(b1, yp1, b0 * yv));
            yp2 = yp1; yp1 = yv;
            float ns = fmaf(na1, s0, fmaf(na2, s1, bx));
            s1 = s0; s0 = ns;
            xr[i] = ns;
        }

        // Backward intra-warp KS (descending).
        v0 = s0; v1 = s1;
        #pragma unroll
        for (int st = 0; st < 2; ++st) {
            const int hc = 1 << st;
            const float* M = PW + 4 * (hc - 1);
            float m00 = M[0], m01 = M[1], m10 = M[2], m11 = M[3];
            float u0 = __shfl_down_sync(0xffffffffu, v0, 8 * hc);
            float u1 = __shfl_down_sync(0xffffffffu, v1, 8 * hc);
            if (g > 3 - hc) { u0 = 0.f; u1 = 0.f; }
            v0 = fmaf(m00, u0, fmaf(m01, u1, v0));
            v1 = fmaf(m10, u0, fmaf(m11, u1, v1));
        }
        E0 = __shfl_down_sync(0xffffffffu, v0, 8);
        E1 = __shfl_down_sync(0xffffffffu, v1, 8);
        if (g == 3) { E0 = 0.f; E1 = 0.f; }
        if (g == 0) {
            VWT[seq * 33 + 2 * wrp]     = v0;
            VWT[seq * 33 + 2 * wrp + 1] = v1;
        }
        __syncthreads();    // B6

        // Backward inter-warp KS (mirror).
        if (wrp < 8) {
            int s = wrp;
            float w0 = 0.f, w1 = 0.f;
            if (lane < 16) {
                w0 = VWT[s * 33 + 2 * lane];
                w1 = VWT[s * 33 + 2 * lane + 1];
            }
            float c = CV[8 + s];
            if (lane == 15) {
                w0 = fmaf(PW[12] + PW[13], c, w0);
                w1 = fmaf(PW[14] + PW[15], c, w1);
            }
            #pragma unroll
            for (int st = 0; st < 3; ++st) {
                const int hc = 1 << st;
                const float* M = (st == 0) ? (PW + 12) : (PK + 4 * (st - 1));
                float m00 = M[0], m01 = M[1], m10 = M[2], m11 = M[3];
                float u0 = __shfl_down_sync(0xffffffffu, w0, hc);
                float u1 = __shfl_down_sync(0xffffffffu, w1, hc);
                if (lane > 15 - hc) { u0 = 0.f; u1 = 0.f; }
                w0 = fmaf(m00, u0, fmaf(m01, u1, w0));
                w1 = fmaf(m10, u0, fmaf(m11, u1, w1));
            }
            float T0 = __shfl_down_sync(0xffffffffu, w0, 1);
            float T1 = __shfl_down_sync(0xffffffffu, w1, 1);
            if (lane == 15) { T0 = c; T1 = c; }
            if (lane < 16) {
                SWT[s * 33 + 2 * lane]     = T0;
                SWT[s * 33 + 2 * lane + 1] = T1;
            }
        }
        __syncthreads();    // B7

        // Backward start state: sb = A^(34(3-g))·T'_w + E'_g.
        float sb0, sb1;
        {
            float T0 = SWT[seq * 33 + 2 * wrp], T1 = SWT[seq * 33 + 2 * wrp + 1];
            if (g == 3) { sb0 = T0; sb1 = T1; }
            else {
                const float* P = PW + 4 * (2 - g);
                sb0 = fmaf(P[0], T0, fmaf(P[1], T1, E0));
                sb1 = fmaf(P[2], T0, fmaf(P[3], T1, E1));
            }
        }

        // Final fix-up + predicated streaming stores (core region only).
        // Store iff (l_local - lo) in [0, LC) with lo = h?128:0 — one compare.
        float* os = out + (size_t)b * Lseq * Dd + (size_t)lbase * Dd + d0 + seq;
        float* ot = os + OUTT;
        const int off = ch * CH - (h ? (LE - LC) : 0);
        #pragma unroll
        for (int i = 0; i < CH; ++i) {
            float2 r = RR[CH - 1 - i];
            float se = fmaf(r.x, sb0, fmaf(r.y, sb1, xr[i]));
            if ((unsigned)(off + i) < (unsigned)LC) {
                __stcs(os + (size_t)i * Dd, se);
                __stcs(ot + (size_t)i * Dd, Y[tid * YSTR + i] - se);
            }
        }
    }
}

extern "C" void kernel_launch(void* const* d_in, const int* in_sizes, int n_in,
                              void* d_out, int out_size)
{
    const float* x  = (const float*)d_in[0];
    const float* bcp = (const float*)d_in[1];
    const float* amp = (const float*)d_in[2];
    float* out = (float*)d_out;

    int dev = 0;
    cudaGetDevice(&dev);
    int sms = 148;
    cudaDeviceGetAttribute(&sms, cudaDevAttrMultiProcessorCount, dev);

    int grid = 2 * sms;                    // 2 blocks per SM (independent phase domains)
    if (grid > TILES) grid = TILES;

    const size_t smem = (size_t)SMEM_FLOATS * sizeof(float);   // ~76.5 KB
    cudaFuncSetAttribute(iir_filtfilt_kernel,
                         cudaFuncAttributeMaxDynamicSharedMemorySize, (int)smem);

    iir_filtfilt_kernel<<<grid, NTH, smem>>>(x, bcp, amp, out);
}